// round 9
// baseline (speedup 1.0000x reference)
#include <cuda_runtime.h>
#include <cstdint>

// KLLoss: mean over rows of -sum_y t[r,y] * log_softmax(p[r])[y]
// N = 4194304 rows, C = 10, fp32. 335.5MB read -> 42us floor @8TB/s.
//
// R9: 4-stage cp.async.bulk pipeline, split consumer groups, producer warp.
//   warp 8           : producer, fills stages round-robin, waits empty mbarrier
//   warps 0-3 (grp 0): consume even chunks (stages 0,2)
//   warps 4-7 (grp 1): consume odd  chunks (stages 1,3)
// Chunk = 640 f4 per array (10KB); stage = pred+tgt = 20KB; 4 stages = 80KB.
// Empty-release happens right after LDS reads -> refill overlaps shuffle/log.
// 296 persistent blocks (2/SM), 16384 chunks total (exact coverage).

#define C 10
#define THREADS 288
#define NWARP 9
#define GRID 296                          // 148 SMs x 2 blocks
#define F4_PER_TILE 160                   // per warp per chunk (64 rows)
#define F4_PER_CHUNK 640                  // 4 consumer warps x 160
#define CHUNK_BYTES 10240                 // per array
#define TOTAL_CHUNKS 16384                // 16384*640 = 10,485,760 f4 exact
#define NSTAGE 4
#define SMEM_BYTES (NSTAGE * 2 * CHUNK_BYTES)   // 81920

__device__ float        g_partials[GRID];
__device__ unsigned int g_count = 0;      // atomicInc wraps -> graph-replay safe

static __device__ __forceinline__ uint32_t smem_u32(const void* p) {
    return (uint32_t)__cvta_generic_to_shared(p);
}
static __device__ __forceinline__ void mbar_init(uint32_t bar, uint32_t cnt) {
    asm volatile("mbarrier.init.shared.b64 [%0], %1;" :: "r"(bar), "r"(cnt) : "memory");
}
static __device__ __forceinline__ void mbar_arrive(uint32_t bar) {
    asm volatile("mbarrier.arrive.shared.b64 _, [%0];" :: "r"(bar) : "memory");
}
static __device__ __forceinline__ void mbar_expect_tx(uint32_t bar, uint32_t bytes) {
    asm volatile("mbarrier.arrive.expect_tx.shared.b64 _, [%0], %1;"
                 :: "r"(bar), "r"(bytes) : "memory");
}
static __device__ __forceinline__ void bulk_g2s(uint32_t dst, const void* src,
                                                uint32_t bytes, uint32_t bar) {
    asm volatile(
        "cp.async.bulk.shared::cluster.global.mbarrier::complete_tx::bytes "
        "[%0], [%1], %2, [%3];"
        :: "r"(dst), "l"(src), "r"(bytes), "r"(bar) : "memory");
}
static __device__ __forceinline__ void mbar_wait(uint32_t bar, uint32_t parity) {
    uint32_t done;
    asm volatile(
        "{\n\t.reg .pred p;\n\t"
        "mbarrier.try_wait.parity.acquire.cta.shared::cta.b64 p, [%1], %2;\n\t"
        "selp.b32 %0, 1, 0, p;\n\t}"
        : "=r"(done) : "r"(bar), "r"(parity) : "memory");
    if (!done) {
        asm volatile(
            "{\n\t.reg .pred P1;\n\t"
            "WL_%=:\n\t"
            "mbarrier.try_wait.parity.acquire.cta.shared::cta.b64 P1, [%0], %1, 0x989680;\n\t"
            "@P1 bra.uni WD_%=;\n\t"
            "bra.uni WL_%=;\n\t"
            "WD_%=:\n\t}"
            :: "r"(bar), "r"(parity) : "memory");
    }
}

__global__ __launch_bounds__(THREADS, 2) void kl_loss_kernel(
    const float4* __restrict__ pred4,
    const float4* __restrict__ tgt4,
    float* __restrict__ out,
    float inv_n)
{
    __shared__ uint64_t mb_full[NSTAGE];
    __shared__ uint64_t mb_empty[NSTAGE];
    __shared__ float    ws[NWARP];
    __shared__ bool     s_last;
    extern __shared__ float4 sdata[];     // [stage][pred 640 | tgt 640]

    const int tid  = threadIdx.x;
    const int lane = tid & 31;
    const int wid  = tid >> 5;
    const unsigned FULL = 0xFFFFFFFFu;
    const int idx1 = (lane + 1) & 31;
    const int idx2 = (lane + 2) & 31;
    const int b    = blockIdx.x;

    const uint32_t sd0 = smem_u32(&sdata[0]);

    if (tid == 0) {
        #pragma unroll
        for (int s = 0; s < NSTAGE; s++) {
            mbar_init(smem_u32(&mb_full[s]), 1);    // producer expect_tx arrive
            mbar_init(smem_u32(&mb_empty[s]), 4);   // 4 consumer-warp arrives
        }
    }
    __syncthreads();

    float acc = 0.0f, dp = 0.0f;

    if (wid == 8) {
        // ---------------- Producer warp (lane 0 only) ----------------
        if (lane == 0) {
            #pragma unroll 1
            for (int k = 0; ; k++) {
                int c = b + k * GRID;
                if (c >= TOTAL_CHUNKS) break;
                int s = k & 3;
                uint32_t fb = smem_u32(&mb_full[s]);
                if (k >= NSTAGE)
                    mbar_wait(smem_u32(&mb_empty[s]), ((k - NSTAGE) >> 2) & 1);
                uint32_t dst = sd0 + (uint32_t)s * 2u * CHUNK_BYTES;
                mbar_expect_tx(fb, 2 * CHUNK_BYTES);
                bulk_g2s(dst,               pred4 + (long)c * F4_PER_CHUNK, CHUNK_BYTES, fb);
                bulk_g2s(dst + CHUNK_BYTES, tgt4  + (long)c * F4_PER_CHUNK, CHUNK_BYTES, fb);
            }
        }
    } else {
        // ---------------- Consumer warps ----------------
        const int g     = wid >> 2;        // group: 0 -> even chunks, 1 -> odd
        const int wslot = wid & 3;
        const int wbase = wslot * F4_PER_TILE;

        #pragma unroll 1
        for (int i = 0; ; i++) {
            int k = g + 2 * i;
            int c = b + k * GRID;
            if (c >= TOTAL_CHUNKS) break;
            int s = k & 3;                 // in {g, g+2}: groups use disjoint stages
            mbar_wait(smem_u32(&mb_full[s]), (k >> 2) & 1);

            const float4* sp = sdata + s * (2 * F4_PER_CHUNK);
            const float4* tp = sp + F4_PER_CHUNK;

            // ---- Per-chunk partials (conflict-free LDS.128) ----
            float lo_e[5], hi_e[5], lo_t[5], hi_t[5];
            #pragma unroll
            for (int j = 0; j < 5; j++) {
                float4 p  = sp[wbase + 32 * j + lane];
                float4 tt = tp[wbase + 32 * j + lane];
                float e0 = __expf(p.x), e1 = __expf(p.y);
                float e2 = __expf(p.z), e3 = __expf(p.w);
                dp = fmaf(tt.x, p.x, fmaf(tt.y, p.y,
                     fmaf(tt.z, p.z, fmaf(tt.w, p.w, dp))));

                int m = (2 * j + lane) % 5;        // global q%5 == (32j+lane)%5
                bool split = (m == 2);
                float e23 = e2 + e3, t23 = tt.z + tt.w;
                lo_e[j] = e0 + e1 + (split ? 0.0f : e23);
                hi_e[j] = split ? e23 : 0.0f;
                lo_t[j] = tt.x + tt.y + (split ? 0.0f : t23);
                hi_t[j] = split ? t23 : 0.0f;
            }

            // All smem reads for this stage are consumed -> release early;
            // the refill overlaps the shuffle/log section below.
            if (lane == 0) mbar_arrive(smem_u32(&mb_empty[s]));

            // ---- Segmented gather, pipelined shuffles (20 SHFL/tile) ----
            float c1e = __shfl_sync(FULL, lo_e[0], idx1);
            float c2e = __shfl_sync(FULL, lo_e[0], idx2);
            float c1t = __shfl_sync(FULL, lo_t[0], idx1);
            float c2t = __shfl_sync(FULL, lo_t[0], idx2);
            #pragma unroll
            for (int j = 0; j < 5; j++) {
                float x1e = 0.0f, x2e = 0.0f, x1t = 0.0f, x2t = 0.0f;
                if (j < 4) {
                    x1e = __shfl_sync(FULL, lo_e[j + 1], idx1);
                    x2e = __shfl_sync(FULL, lo_e[j + 1], idx2);
                    x1t = __shfl_sync(FULL, lo_t[j + 1], idx1);
                    x2t = __shfl_sync(FULL, lo_t[j + 1], idx2);
                }
                float n1e = (lane < 31) ? c1e : x1e;   // lane31 -> slot j+1 lane0
                float n2e = (lane < 30) ? c2e : x2e;   // lanes30/31 -> j+1 lanes0/1
                float n1t = (lane < 31) ? c1t : x1t;
                float n2t = (lane < 30) ? c2t : x2t;

                int m = (2 * j + lane) % 5;
                if (m == 0)
                    acc += __logf(lo_e[j] + n1e + n2e) * (lo_t[j] + n1t + n2t);
                if (m == 2)
                    acc += __logf(hi_e[j] + n1e + n2e) * (hi_t[j] + n1t + n2t);

                c1e = x1e; c2e = x2e; c1t = x1t; c2t = x2t;
            }
        }
    }
    acc -= dp;

    // ---- Block reduce over all 9 warps (producer contributes 0) ----
    #pragma unroll
    for (int off = 16; off > 0; off >>= 1)
        acc += __shfl_xor_sync(FULL, acc, off);
    if (lane == 0) ws[wid] = acc;
    __syncthreads();

    if (tid == 0) {
        float bsum = 0.0f;
        #pragma unroll
        for (int i = 0; i < NWARP; i++) bsum += ws[i];
        g_partials[b] = bsum;
        __threadfence();
        unsigned old = atomicInc(&g_count, GRID - 1);    // self-resets
        s_last = (old == GRID - 1);
    }
    __syncthreads();

    // ---- Last block: final reduction ----
    if (s_last) {
        float v = 0.0f;
        for (int i = tid; i < GRID; i += THREADS)
            v += __ldcg(&g_partials[i]);
        #pragma unroll
        for (int off = 16; off > 0; off >>= 1)
            v += __shfl_xor_sync(FULL, v, off);
        if (lane == 0) ws[wid] = v;
        __syncthreads();
        if (tid < 32) {
            float x = (tid < NWARP) ? ws[tid] : 0.0f;
            #pragma unroll
            for (int off = 16; off > 0; off >>= 1)
                x += __shfl_xor_sync(FULL, x, off);
            if (tid == 0) out[0] = x * inv_n;
        }
    }
}

extern "C" void kernel_launch(void* const* d_in, const int* in_sizes, int n_in,
                              void* d_out, int out_size) {
    const float4* pred = (const float4*)d_in[0];
    const float4* tgt  = (const float4*)d_in[1];
    float* out = (float*)d_out;

    static bool attr_set = false;
    if (!attr_set) {
        cudaFuncSetAttribute(kl_loss_kernel,
                             cudaFuncAttributeMaxDynamicSharedMemorySize,
                             SMEM_BYTES);
        attr_set = true;
    }

    int n_rows  = in_sizes[0] / C;          // 4,194,304
    float inv_n = 1.0f / (float)n_rows;
    kl_loss_kernel<<<GRID, THREADS, SMEM_BYTES>>>(pred, tgt, out, inv_n);
}

// round 10
// speedup vs baseline: 1.0696x; 1.0696x over previous
#include <cuda_runtime.h>
#include <cstdint>

// KLLoss: mean over rows of -sum_y t[r,y] * log_softmax(p[r])[y]
// N = 4194304 rows, C = 10, fp32. 335.5MB read.
//
// R10 (= R8 verbatim, convergence lock-in): cp.async.bulk double-buffered
// smem pipeline at the measured LTS ceiling (~6.22 TB/s, path-independent).
// Floor at this ceiling = 53.9us; R8 kernel = 54.59us (98.7%).
// One elected thread issues 2x20KB bulk copies/chunk; mbarrier complete_tx
// signals arrival; compute warps read conflict-free LDS.128 and run the
// validated segmented row reduction (rel_err 6.99e-08 across 5 runs).
// 296 persistent blocks (2/SM, 80KB smem), 8192 chunks of 1280 f4 (exact).

#define C 10
#define THREADS 256
#define WARPS_PER_BLOCK 8
#define GRID 296                          // 148 SMs x 2 blocks
#define F4_PER_TILE 160                   // per warp per chunk (64 rows)
#define F4_PER_CHUNK 1280                 // 8 warps x 160
#define CHUNK_BYTES 20480                 // per array
#define TOTAL_CHUNKS 8192                 // 8192*1280 = 10,485,760 f4 exact
#define SMEM_BYTES (2 * 2 * CHUNK_BYTES)  // 2 stages x (pred+tgt) = 81920

__device__ float        g_partials[GRID];
__device__ unsigned int g_count = 0;      // atomicInc wraps -> graph-replay safe

static __device__ __forceinline__ uint32_t smem_u32(const void* p) {
    return (uint32_t)__cvta_generic_to_shared(p);
}

static __device__ __forceinline__ void mbar_init(uint32_t bar, uint32_t cnt) {
    asm volatile("mbarrier.init.shared.b64 [%0], %1;" :: "r"(bar), "r"(cnt) : "memory");
}
static __device__ __forceinline__ void mbar_expect_tx(uint32_t bar, uint32_t bytes) {
    asm volatile("mbarrier.arrive.expect_tx.shared.b64 _, [%0], %1;"
                 :: "r"(bar), "r"(bytes) : "memory");
}
static __device__ __forceinline__ void bulk_g2s(uint32_t dst, const void* src,
                                                uint32_t bytes, uint32_t bar) {
    asm volatile(
        "cp.async.bulk.shared::cluster.global.mbarrier::complete_tx::bytes "
        "[%0], [%1], %2, [%3];"
        :: "r"(dst), "l"(src), "r"(bytes), "r"(bar) : "memory");
}
static __device__ __forceinline__ void mbar_wait(uint32_t bar, uint32_t parity) {
    uint32_t done;
    asm volatile(
        "{\n\t.reg .pred p;\n\t"
        "mbarrier.try_wait.parity.acquire.cta.shared::cta.b64 p, [%1], %2;\n\t"
        "selp.b32 %0, 1, 0, p;\n\t}"
        : "=r"(done) : "r"(bar), "r"(parity) : "memory");
    if (!done) {
        asm volatile(
            "{\n\t.reg .pred P1;\n\t"
            "WL_%=:\n\t"
            "mbarrier.try_wait.parity.acquire.cta.shared::cta.b64 P1, [%0], %1, 0x989680;\n\t"
            "@P1 bra.uni WD_%=;\n\t"
            "bra.uni WL_%=;\n\t"
            "WD_%=:\n\t}"
            :: "r"(bar), "r"(parity) : "memory");
    }
}

__global__ __launch_bounds__(THREADS, 2) void kl_loss_kernel(
    const float4* __restrict__ pred4,
    const float4* __restrict__ tgt4,
    float* __restrict__ out,
    float inv_n)
{
    __shared__ uint64_t mbar_full[2];
    __shared__ float    ws[WARPS_PER_BLOCK];
    __shared__ bool     s_last;
    extern __shared__ float4 sdata[];     // [stage][2][1280]

    const int tid  = threadIdx.x;
    const int lane = tid & 31;
    const int wid  = tid >> 5;
    const unsigned FULL = 0xFFFFFFFFu;
    const int idx1 = (lane + 1) & 31;
    const int idx2 = (lane + 2) & 31;
    const int b    = blockIdx.x;

    const uint32_t bar0 = smem_u32(&mbar_full[0]);
    const uint32_t bar1 = smem_u32(&mbar_full[1]);
    const uint32_t sd0  = smem_u32(&sdata[0]);

    if (tid == 0) { mbar_init(bar0, 1); mbar_init(bar1, 1); }
    __syncthreads();

    // ---- Prologue: fill both stages ----
    if (tid == 0) {
        #pragma unroll
        for (int s = 0; s < 2; s++) {
            int c = b + s * GRID;
            if (c < TOTAL_CHUNKS) {
                uint32_t bar = s ? bar1 : bar0;
                uint32_t dst = sd0 + (uint32_t)s * 2u * CHUNK_BYTES;
                mbar_expect_tx(bar, 2 * CHUNK_BYTES);
                bulk_g2s(dst,               pred4 + (long)c * F4_PER_CHUNK, CHUNK_BYTES, bar);
                bulk_g2s(dst + CHUNK_BYTES, tgt4  + (long)c * F4_PER_CHUNK, CHUNK_BYTES, bar);
            }
        }
    }

    float acc = 0.0f, dp = 0.0f;

    #pragma unroll 1
    for (int k = 0; b + k * GRID < TOTAL_CHUNKS; k++) {
        const int s = k & 1;
        mbar_wait(s ? bar1 : bar0, (k >> 1) & 1);

        const float4* sp = sdata + s * (2 * F4_PER_CHUNK);
        const float4* tp = sp + F4_PER_CHUNK;
        const int wbase = wid * F4_PER_TILE;

        // ---- Per-chunk partials (conflict-free LDS.128) ----
        float lo_e[5], hi_e[5], lo_t[5], hi_t[5];
        #pragma unroll
        for (int j = 0; j < 5; j++) {
            float4 p  = sp[wbase + 32 * j + lane];
            float4 tt = tp[wbase + 32 * j + lane];
            float e0 = __expf(p.x), e1 = __expf(p.y);
            float e2 = __expf(p.z), e3 = __expf(p.w);
            dp = fmaf(tt.x, p.x, fmaf(tt.y, p.y,
                 fmaf(tt.z, p.z, fmaf(tt.w, p.w, dp))));

            int m = (2 * j + lane) % 5;          // q%5, q = 32j + lane
            bool split = (m == 2);
            float e23 = e2 + e3, t23 = tt.z + tt.w;
            lo_e[j] = e0 + e1 + (split ? 0.0f : e23);
            hi_e[j] = split ? e23 : 0.0f;
            lo_t[j] = tt.x + tt.y + (split ? 0.0f : t23);
            hi_t[j] = split ? t23 : 0.0f;
        }

        // ---- Segmented gather, pipelined shuffles (20 SHFL/tile) ----
        float c1e = __shfl_sync(FULL, lo_e[0], idx1);
        float c2e = __shfl_sync(FULL, lo_e[0], idx2);
        float c1t = __shfl_sync(FULL, lo_t[0], idx1);
        float c2t = __shfl_sync(FULL, lo_t[0], idx2);
        #pragma unroll
        for (int j = 0; j < 5; j++) {
            float x1e = 0.0f, x2e = 0.0f, x1t = 0.0f, x2t = 0.0f;
            if (j < 4) {
                x1e = __shfl_sync(FULL, lo_e[j + 1], idx1);
                x2e = __shfl_sync(FULL, lo_e[j + 1], idx2);
                x1t = __shfl_sync(FULL, lo_t[j + 1], idx1);
                x2t = __shfl_sync(FULL, lo_t[j + 1], idx2);
            }
            float n1e = (lane < 31) ? c1e : x1e;   // lane31 wraps to slot j+1 lane0
            float n2e = (lane < 30) ? c2e : x2e;   // lanes30/31 -> j+1 lanes0/1
            float n1t = (lane < 31) ? c1t : x1t;
            float n2t = (lane < 30) ? c2t : x2t;

            int m = (2 * j + lane) % 5;
            if (m == 0)
                acc += __logf(lo_e[j] + n1e + n2e) * (lo_t[j] + n1t + n2t);
            if (m == 2)
                acc += __logf(hi_e[j] + n1e + n2e) * (hi_t[j] + n1t + n2t);

            c1e = x1e; c2e = x2e; c1t = x1t; c2t = x2t;
        }

        __syncthreads();   // all warps done with stage s

        // ---- Refill stage s with chunk k+2 ----
        int cn = b + (k + 2) * GRID;
        if (tid == 0 && cn < TOTAL_CHUNKS) {
            asm volatile("fence.proxy.async.shared::cta;" ::: "memory");
            uint32_t bar = s ? bar1 : bar0;
            uint32_t dst = sd0 + (uint32_t)s * 2u * CHUNK_BYTES;
            mbar_expect_tx(bar, 2 * CHUNK_BYTES);
            bulk_g2s(dst,               pred4 + (long)cn * F4_PER_CHUNK, CHUNK_BYTES, bar);
            bulk_g2s(dst + CHUNK_BYTES, tgt4  + (long)cn * F4_PER_CHUNK, CHUNK_BYTES, bar);
        }
    }
    acc -= dp;

    // ---- Block reduce ----
    #pragma unroll
    for (int off = 16; off > 0; off >>= 1)
        acc += __shfl_xor_sync(FULL, acc, off);
    if (lane == 0) ws[wid] = acc;
    __syncthreads();

    if (tid == 0) {
        float bsum = 0.0f;
        #pragma unroll
        for (int i = 0; i < WARPS_PER_BLOCK; i++) bsum += ws[i];
        g_partials[b] = bsum;
        __threadfence();
        unsigned old = atomicInc(&g_count, GRID - 1);    // self-resets
        s_last = (old == GRID - 1);
    }
    __syncthreads();

    // ---- Last block: final reduction ----
    if (s_last) {
        float v = 0.0f;
        for (int i = tid; i < GRID; i += THREADS)
            v += __ldcg(&g_partials[i]);
        #pragma unroll
        for (int off = 16; off > 0; off >>= 1)
            v += __shfl_xor_sync(FULL, v, off);
        if (lane == 0) ws[wid] = v;
        __syncthreads();
        if (tid < 32) {
            float x = (tid < WARPS_PER_BLOCK) ? ws[tid] : 0.0f;
            #pragma unroll
            for (int off = 4; off > 0; off >>= 1)
                x += __shfl_xor_sync(FULL, x, off);
            if (tid == 0) out[0] = x * inv_n;
        }
    }
}

extern "C" void kernel_launch(void* const* d_in, const int* in_sizes, int n_in,
                              void* d_out, int out_size) {
    const float4* pred = (const float4*)d_in[0];
    const float4* tgt  = (const float4*)d_in[1];
    float* out = (float*)d_out;

    static bool attr_set = false;
    if (!attr_set) {
        cudaFuncSetAttribute(kl_loss_kernel,
                             cudaFuncAttributeMaxDynamicSharedMemorySize,
                             SMEM_BYTES);
        attr_set = true;
    }

    int n_rows  = in_sizes[0] / C;          // 4,194,304
    float inv_n = 1.0f / (float)n_rows;
    kl_loss_kernel<<<GRID, THREADS, SMEM_BYTES>>>(pred, tgt, out, inv_n);
}